// round 2
// baseline (speedup 1.0000x reference)
#include <cuda_runtime.h>
#include <math.h>

#define BB 2
#define HH 16
#define SS 2048
#define DKK 128
#define DM 2048
#define MT (BB*SS) // 4096

// Scratch (device globals: allocation-guard-safe)
__device__ float g_Q[BB*HH*SS*DKK];
__device__ float g_K[BB*HH*SS*DKK];
__device__ float g_V[BB*HH*SS*DKK];
__device__ float g_AO[MT*DM];

// ---------------------------------------------------------------------------
// Fused QKV projection GEMM + RoPE epilogue.
// Y = X[4096,2048] @ W[2048,2048]; z=0:Wq(rope) 1:Wk(rope) 2:Wv(no rope)
// Output scattered to [B,H,S,128] layout.
// Tiles: BM=128, BN=64, BK=16; 256 threads; thread tile 8x4.
// ---------------------------------------------------------------------------
__global__ __launch_bounds__(256) void qkv_gemm(
    const float* __restrict__ X,
    const float* __restrict__ Wq, const float* __restrict__ Wk,
    const float* __restrict__ Wv,
    const int* __restrict__ tok)
{
    __shared__ float As[16*132];  // transposed: As[k][m], row stride 132
    __shared__ float Bs[16*68];   // Bs[k][n], row stride 68

    const int z = blockIdx.z;
    const float* __restrict__ W = (z == 0) ? Wq : ((z == 1) ? Wk : Wv);
    float* __restrict__ out = (z == 0) ? g_Q : ((z == 1) ? g_K : g_V);

    const int n0 = blockIdx.x * 64;
    const int m0 = blockIdx.y * 128;
    const int t  = threadIdx.x;
    const int tx = t & 15;
    const int ty = t >> 4;

    float acc[8][4];
#pragma unroll
    for (int i = 0; i < 8; i++)
#pragma unroll
        for (int j = 0; j < 4; j++) acc[i][j] = 0.f;

    // A tile: 128 rows x 16 k = 512 float4; 2 per thread
    const int af0 = t * 2, af1 = t * 2 + 1;
    const int ar0 = af0 >> 2, ac0 = (af0 & 3) * 4;
    const int ar1 = af1 >> 2, ac1 = (af1 & 3) * 4;
    // B tile: 16 k x 64 n = 256 float4; 1 per thread
    const int br = t >> 4, bc = (t & 15) * 4;

    for (int k0 = 0; k0 < DM; k0 += 16) {
        const float4 a0 = *(const float4*)&X[(size_t)(m0 + ar0) * DM + k0 + ac0];
        const float4 a1 = *(const float4*)&X[(size_t)(m0 + ar1) * DM + k0 + ac1];
        const float4 bv = *(const float4*)&W[(size_t)(k0 + br) * DM + n0 + bc];
        __syncthreads();
        As[(ac0 + 0) * 132 + ar0] = a0.x;
        As[(ac0 + 1) * 132 + ar0] = a0.y;
        As[(ac0 + 2) * 132 + ar0] = a0.z;
        As[(ac0 + 3) * 132 + ar0] = a0.w;
        As[(ac1 + 0) * 132 + ar1] = a1.x;
        As[(ac1 + 1) * 132 + ar1] = a1.y;
        As[(ac1 + 2) * 132 + ar1] = a1.z;
        As[(ac1 + 3) * 132 + ar1] = a1.w;
        *(float4*)&Bs[br * 68 + bc] = bv;
        __syncthreads();

#pragma unroll
        for (int kk = 0; kk < 16; kk++) {
            const float4 aa0 = *(const float4*)&As[kk * 132 + ty * 8];
            const float4 aa1 = *(const float4*)&As[kk * 132 + ty * 8 + 4];
            const float4 bb  = *(const float4*)&Bs[kk * 68 + tx * 4];
            const float av[8] = {aa0.x, aa0.y, aa0.z, aa0.w,
                                 aa1.x, aa1.y, aa1.z, aa1.w};
            const float bw[4] = {bb.x, bb.y, bb.z, bb.w};
#pragma unroll
            for (int i = 0; i < 8; i++)
#pragma unroll
                for (int j = 0; j < 4; j++)
                    acc[i][j] += av[i] * bw[j];
        }
    }

    // Epilogue: scatter to [B,H,S,128]; RoPE for z<2
    const float RLOG = -0.07195578146f; // -ln(10000)/128
#pragma unroll
    for (int i = 0; i < 8; i++) {
        const int m = m0 + ty * 8 + i;
        const int s = m & (SS - 1);
        const int b = m >> 11;
        if (z < 2) {
            const float pos = (float)tok[s];
#pragma unroll
            for (int jp = 0; jp < 4; jp += 2) {
                const int n = n0 + tx * 4 + jp;
                const int c = n & (DKK - 1);
                const int h = n >> 7;
                const float freq = expf((float)c * RLOG);
                const float ang = pos * freq;
                float sv, cv;
                sincosf(ang, &sv, &cv);
                const float x1 = acc[i][jp], x2 = acc[i][jp + 1];
                float* o = &out[((size_t)(b * HH + h) * SS + s) * DKK + c];
                o[0] = x1 * cv - x2 * sv;
                o[1] = x1 * sv + x2 * cv;
            }
        } else {
            const int n = n0 + tx * 4;
            const int c = n & (DKK - 1);
            const int h = n >> 7;
            *(float4*)&out[((size_t)(b * HH + h) * SS + s) * DKK + c] =
                make_float4(acc[i][0], acc[i][1], acc[i][2], acc[i][3]);
        }
    }
}

// ---------------------------------------------------------------------------
// Flash attention, fp32, causal. BM=BN=32, 256 threads.
// Thread (tx,ty): scores rows ty*2+{0,1}, cols tx*2+{0,1};
// output rows ty*2+{0,1}, cols {tx*4..tx*4+3} U {64+tx*4..64+tx*4+3}.
// K stored transposed (d-major) in smem; V row-major (shared buffer).
// ---------------------------------------------------------------------------
__global__ __launch_bounds__(256) void attn_kernel()
{
    __shared__ float Qs[32 * 132];
    __shared__ float KV[4480];     // max(Kt 128*34=4352, V 32*132=4224)
    __shared__ float Ps[32 * 36];

    const int qb = blockIdx.x;     // 0..63
    const int bh = blockIdx.y;     // 0..31
    const int q0 = qb * 32;
    const int t  = threadIdx.x;
    const int tx = t & 15;
    const int ty = t >> 4;
    const size_t base = (size_t)bh * SS * DKK;

    const int lrw = t >> 3;        // 0..31: row for tile loads
    const int lf  = t & 7;         // 0..7:  float4 lane for tile loads

    // Load Q tile [32][128]
    {
        const float* qsrc = &g_Q[base + (size_t)(q0 + lrw) * DKK];
#pragma unroll
        for (int j = 0; j < 4; j++) {
            const float4 v = *(const float4*)&qsrc[(lf + j * 8) * 4];
            *(float4*)&Qs[lrw * 132 + (lf + j * 8) * 4] = v;
        }
    }

    float o[2][8];
#pragma unroll
    for (int i = 0; i < 2; i++)
#pragma unroll
        for (int c = 0; c < 8; c++) o[i][c] = 0.f;
    float mrow[2] = {-1e30f, -1e30f};
    float lrow[2] = {0.f, 0.f};
    const float scale = 0.0883883476483f;  // 1/sqrt(128)

    __syncthreads();

    for (int kb = 0; kb <= qb; kb++) {
        const int k0 = kb * 32;
        // Load K tile transposed: Kt[d][key], stride 34
        {
            const float* ks = &g_K[base + (size_t)(k0 + lrw) * DKK];
#pragma unroll
            for (int j = 0; j < 4; j++) {
                const float4 v = *(const float4*)&ks[(lf + j * 8) * 4];
                const int c0 = (lf + j * 8) * 4;
                KV[(c0 + 0) * 34 + lrw] = v.x;
                KV[(c0 + 1) * 34 + lrw] = v.y;
                KV[(c0 + 2) * 34 + lrw] = v.z;
                KV[(c0 + 3) * 34 + lrw] = v.w;
            }
        }
        __syncthreads();

        // GEMM1: S = Q K^T
        float sacc[2][2] = {{0.f, 0.f}, {0.f, 0.f}};
#pragma unroll 8
        for (int d = 0; d < DKK; d++) {
            const float qv0 = Qs[(ty * 2 + 0) * 132 + d];
            const float qv1 = Qs[(ty * 2 + 1) * 132 + d];
            const float2 kk = *(const float2*)&KV[d * 34 + tx * 2];
            sacc[0][0] += qv0 * kk.x;
            sacc[0][1] += qv0 * kk.y;
            sacc[1][0] += qv1 * kk.x;
            sacc[1][1] += qv1 * kk.y;
        }

        // Online softmax
        const bool diag = (kb == qb);
#pragma unroll
        for (int i = 0; i < 2; i++) {
            const int qi = q0 + ty * 2 + i;
            float s0 = sacc[i][0] * scale;
            float s1 = sacc[i][1] * scale;
            if (diag) {
                if (k0 + tx * 2 + 0 > qi) s0 = -1e30f;
                if (k0 + tx * 2 + 1 > qi) s1 = -1e30f;
            }
            float mx = fmaxf(s0, s1);
#pragma unroll
            for (int off = 1; off < 16; off <<= 1)
                mx = fmaxf(mx, __shfl_xor_sync(0xffffffffu, mx, off));
            const float mnew = fmaxf(mrow[i], mx);
            const float alpha = expf(mrow[i] - mnew);
            const float p0 = expf(s0 - mnew);
            const float p1 = expf(s1 - mnew);
            float ls = p0 + p1;
#pragma unroll
            for (int off = 1; off < 16; off <<= 1)
                ls += __shfl_xor_sync(0xffffffffu, ls, off);
            lrow[i] = lrow[i] * alpha + ls;
            mrow[i] = mnew;
#pragma unroll
            for (int c = 0; c < 8; c++) o[i][c] *= alpha;
            Ps[(ty * 2 + i) * 36 + tx * 2 + 0] = p0;
            Ps[(ty * 2 + i) * 36 + tx * 2 + 1] = p1;
        }
        __syncthreads();  // Ps written; K reads done

        // Load V tile row-major into same buffer
        {
            const float* vs = &g_V[base + (size_t)(k0 + lrw) * DKK];
#pragma unroll
            for (int j = 0; j < 4; j++) {
                const float4 v = *(const float4*)&vs[(lf + j * 8) * 4];
                *(float4*)&KV[lrw * 132 + (lf + j * 8) * 4] = v;
            }
        }
        __syncthreads();

        // GEMM2: O += P V
#pragma unroll 8
        for (int j = 0; j < 32; j++) {
            const float p0 = Ps[(ty * 2 + 0) * 36 + j];
            const float p1 = Ps[(ty * 2 + 1) * 36 + j];
            const float4 va = *(const float4*)&KV[j * 132 + tx * 4];
            const float4 vb = *(const float4*)&KV[j * 132 + 64 + tx * 4];
            o[0][0] += p0 * va.x; o[0][1] += p0 * va.y;
            o[0][2] += p0 * va.z; o[0][3] += p0 * va.w;
            o[0][4] += p0 * vb.x; o[0][5] += p0 * vb.y;
            o[0][6] += p0 * vb.z; o[0][7] += p0 * vb.w;
            o[1][0] += p1 * va.x; o[1][1] += p1 * va.y;
            o[1][2] += p1 * va.z; o[1][3] += p1 * va.w;
            o[1][4] += p1 * vb.x; o[1][5] += p1 * vb.y;
            o[1][6] += p1 * vb.z; o[1][7] += p1 * vb.w;
        }
        __syncthreads();  // KV/Ps consumed; safe to overwrite next iter
    }

    // Finalize: O /= l; write to [B,S,H*128]
    const int b = bh >> 4;
    const int h = bh & 15;
#pragma unroll
    for (int i = 0; i < 2; i++) {
        const float inv = 1.f / lrow[i];
        const int s = q0 + ty * 2 + i;
        const size_t ob = ((size_t)b * SS + s) * DM + h * DKK;
        *(float4*)&g_AO[ob + tx * 4] =
            make_float4(o[i][0] * inv, o[i][1] * inv, o[i][2] * inv, o[i][3] * inv);
        *(float4*)&g_AO[ob + 64 + tx * 4] =
            make_float4(o[i][4] * inv, o[i][5] * inv, o[i][6] * inv, o[i][7] * inv);
    }
}

// ---------------------------------------------------------------------------
// Output projection GEMM: d_out = AO[4096,2048] @ Wo[2048,2048]
// Same tiling as qkv_gemm, plain row-major store.
// ---------------------------------------------------------------------------
__global__ __launch_bounds__(256) void out_gemm(
    const float* __restrict__ Wo, float* __restrict__ outp)
{
    __shared__ float As[16*132];
    __shared__ float Bs[16*68];

    const int n0 = blockIdx.x * 64;
    const int m0 = blockIdx.y * 128;
    const int t  = threadIdx.x;
    const int tx = t & 15;
    const int ty = t >> 4;

    float acc[8][4];
#pragma unroll
    for (int i = 0; i < 8; i++)
#pragma unroll
        for (int j = 0; j < 4; j++) acc[i][j] = 0.f;

    const int af0 = t * 2, af1 = t * 2 + 1;
    const int ar0 = af0 >> 2, ac0 = (af0 & 3) * 4;
    const int ar1 = af1 >> 2, ac1 = (af1 & 3) * 4;
    const int br = t >> 4, bc = (t & 15) * 4;

    for (int k0 = 0; k0 < DM; k0 += 16) {
        const float4 a0 = *(const float4*)&g_AO[(size_t)(m0 + ar0) * DM + k0 + ac0];
        const float4 a1 = *(const float4*)&g_AO[(size_t)(m0 + ar1) * DM + k0 + ac1];
        const float4 bv = *(const float4*)&Wo[(size_t)(k0 + br) * DM + n0 + bc];
        __syncthreads();
        As[(ac0 + 0) * 132 + ar0] = a0.x;
        As[(ac0 + 1) * 132 + ar0] = a0.y;
        As[(ac0 + 2) * 132 + ar0] = a0.z;
        As[(ac0 + 3) * 132 + ar0] = a0.w;
        As[(ac1 + 0) * 132 + ar1] = a1.x;
        As[(ac1 + 1) * 132 + ar1] = a1.y;
        As[(ac1 + 2) * 132 + ar1] = a1.z;
        As[(ac1 + 3) * 132 + ar1] = a1.w;
        *(float4*)&Bs[br * 68 + bc] = bv;
        __syncthreads();

#pragma unroll
        for (int kk = 0; kk < 16; kk++) {
            const float4 aa0 = *(const float4*)&As[kk * 132 + ty * 8];
            const float4 aa1 = *(const float4*)&As[kk * 132 + ty * 8 + 4];
            const float4 bb  = *(const float4*)&Bs[kk * 68 + tx * 4];
            const float av[8] = {aa0.x, aa0.y, aa0.z, aa0.w,
                                 aa1.x, aa1.y, aa1.z, aa1.w};
            const float bw[4] = {bb.x, bb.y, bb.z, bb.w};
#pragma unroll
            for (int i = 0; i < 8; i++)
#pragma unroll
                for (int j = 0; j < 4; j++)
                    acc[i][j] += av[i] * bw[j];
        }
    }

#pragma unroll
    for (int i = 0; i < 8; i++) {
        *(float4*)&outp[(size_t)(m0 + ty * 8 + i) * DM + n0 + tx * 4] =
            make_float4(acc[i][0], acc[i][1], acc[i][2], acc[i][3]);
    }
}

// ---------------------------------------------------------------------------
extern "C" void kernel_launch(void* const* d_in, const int* in_sizes, int n_in,
                              void* d_out, int out_size)
{
    const float* x  = (const float*)d_in[0];
    const float* Wq = (const float*)d_in[1];
    const float* Wk = (const float*)d_in[2];
    const float* Wv = (const float*)d_in[3];
    const float* Wo = (const float*)d_in[4];
    const int*  tok = (const int*)d_in[5];
    float* outp = (float*)d_out;

    qkv_gemm<<<dim3(DM / 64, MT / 128, 3), 256>>>(x, Wq, Wk, Wv, tok);
    attn_kernel<<<dim3(SS / 32, BB * HH), 256>>>();
    out_gemm<<<dim3(DM / 64, MT / 128), 256>>>(Wo, outp);
}

// round 4
// speedup vs baseline: 1.6237x; 1.6237x over previous
#include <cuda_runtime.h>
#include <math.h>

#define BB 2
#define HH 16
#define SS 2048
#define DKK 128
#define DM 2048
#define MT (BB*SS) // 4096

// Scratch (device globals: allocation-guard-safe)
__device__ float g_Q[BB*HH*SS*DKK];
__device__ float g_K[BB*HH*SS*DKK];
__device__ float g_V[BB*HH*SS*DKK];
__device__ float g_AO[MT*DM];

// ---------------------------------------------------------------------------
// TF32 helpers
// ---------------------------------------------------------------------------
__device__ __forceinline__ unsigned f2tf32(float x) {
    unsigned u;
    asm("cvt.rna.tf32.f32 %0, %1;" : "=r"(u) : "f"(x));
    return u;
}

__device__ __forceinline__ void mma_tf32(float* c, const unsigned* a, const unsigned* b) {
    asm volatile(
        "mma.sync.aligned.m16n8k8.row.col.f32.tf32.tf32.f32 "
        "{%0,%1,%2,%3}, {%4,%5,%6,%7}, {%8,%9}, {%0,%1,%2,%3};\n"
        : "+f"(c[0]), "+f"(c[1]), "+f"(c[2]), "+f"(c[3])
        : "r"(a[0]), "r"(a[1]), "r"(a[2]), "r"(a[3]), "r"(b[0]), "r"(b[1]));
}

// ---------------------------------------------------------------------------
// TF32 tensor-core GEMM core.
// Block tile 128m x 128n x 16k, 256 threads = 8 warps (2m x 4n),
// warp tile 64x32 = 4x4 m16n8k8 fragments.
// smem layout: As[k][m] / Bs[k][n], row stride 136 (8k+m covers all banks).
// ---------------------------------------------------------------------------
#define SM_STRIDE 136

// Fused QKV projection + RoPE epilogue. z=0:Q(rope) 1:K(rope) 2:V
__global__ __launch_bounds__(256, 2) void qkv_gemm(
    const float* __restrict__ X,
    const float* __restrict__ Wq, const float* __restrict__ Wk,
    const float* __restrict__ Wv,
    const int* __restrict__ tok)
{
    __shared__ unsigned As[16 * SM_STRIDE];
    __shared__ unsigned Bs[16 * SM_STRIDE];

    const int z = blockIdx.z;
    const float* __restrict__ W = (z == 0) ? Wq : ((z == 1) ? Wk : Wv);
    float* __restrict__ out = (z == 0) ? g_Q : ((z == 1) ? g_K : g_V);

    const int n0 = blockIdx.x * 128;
    const int m0 = blockIdx.y * 128;
    const int t    = threadIdx.x;
    const int lane = t & 31;
    const int warp = t >> 5;
    const int wm = warp >> 2;       // 0..1
    const int wn = warp & 3;        // 0..3
    const int g  = lane >> 2;       // 0..7
    const int tg = lane & 3;        // 0..3

    // Loader indices
    const int arow  = t >> 1;            // 0..127
    const int akoff = (t & 1) * 8;       // 0 or 8
    const int brow  = t >> 4;            // 0..15
    const int bn    = (t & 15) * 8;      // 0..120

    float acc[4][4][4];
#pragma unroll
    for (int mf = 0; mf < 4; mf++)
#pragma unroll
        for (int nf = 0; nf < 4; nf++)
#pragma unroll
            for (int r = 0; r < 4; r++) acc[mf][nf][r] = 0.f;

    for (int k0 = 0; k0 < DM; k0 += 16) {
        const float4 a0 = *(const float4*)&X[(size_t)(m0 + arow) * DM + k0 + akoff];
        const float4 a1 = *(const float4*)&X[(size_t)(m0 + arow) * DM + k0 + akoff + 4];
        const float4 b0 = *(const float4*)&W[(size_t)(k0 + brow) * DM + n0 + bn];
        const float4 b1 = *(const float4*)&W[(size_t)(k0 + brow) * DM + n0 + bn + 4];
        __syncthreads();
        As[(akoff + 0) * SM_STRIDE + arow] = f2tf32(a0.x);
        As[(akoff + 1) * SM_STRIDE + arow] = f2tf32(a0.y);
        As[(akoff + 2) * SM_STRIDE + arow] = f2tf32(a0.z);
        As[(akoff + 3) * SM_STRIDE + arow] = f2tf32(a0.w);
        As[(akoff + 4) * SM_STRIDE + arow] = f2tf32(a1.x);
        As[(akoff + 5) * SM_STRIDE + arow] = f2tf32(a1.y);
        As[(akoff + 6) * SM_STRIDE + arow] = f2tf32(a1.z);
        As[(akoff + 7) * SM_STRIDE + arow] = f2tf32(a1.w);
        Bs[brow * SM_STRIDE + bn + 0] = f2tf32(b0.x);
        Bs[brow * SM_STRIDE + bn + 1] = f2tf32(b0.y);
        Bs[brow * SM_STRIDE + bn + 2] = f2tf32(b0.z);
        Bs[brow * SM_STRIDE + bn + 3] = f2tf32(b0.w);
        Bs[brow * SM_STRIDE + bn + 4] = f2tf32(b1.x);
        Bs[brow * SM_STRIDE + bn + 5] = f2tf32(b1.y);
        Bs[brow * SM_STRIDE + bn + 6] = f2tf32(b1.z);
        Bs[brow * SM_STRIDE + bn + 7] = f2tf32(b1.w);
        __syncthreads();

#pragma unroll
        for (int ks = 0; ks < 16; ks += 8) {
            unsigned a[4][4];
#pragma unroll
            for (int mf = 0; mf < 4; mf++) {
                const int mb = wm * 64 + mf * 16 + g;
                a[mf][0] = As[(ks + tg) * SM_STRIDE + mb];
                a[mf][1] = As[(ks + tg) * SM_STRIDE + mb + 8];
                a[mf][2] = As[(ks + tg + 4) * SM_STRIDE + mb];
                a[mf][3] = As[(ks + tg + 4) * SM_STRIDE + mb + 8];
            }
            unsigned b[4][2];
#pragma unroll
            for (int nf = 0; nf < 4; nf++) {
                const int nb = wn * 32 + nf * 8 + g;
                b[nf][0] = Bs[(ks + tg) * SM_STRIDE + nb];
                b[nf][1] = Bs[(ks + tg + 4) * SM_STRIDE + nb];
            }
#pragma unroll
            for (int mf = 0; mf < 4; mf++)
#pragma unroll
                for (int nf = 0; nf < 4; nf++)
                    mma_tf32(acc[mf][nf], a[mf], b[nf]);
        }
    }

    // Epilogue: c0,c1 are cols (2tg, 2tg+1) = a RoPE pair; c2,c3 same at row+8.
    const float RLOG = -0.07195578146f; // -ln(10000)/128
#pragma unroll
    for (int mf = 0; mf < 4; mf++) {
#pragma unroll
        for (int nf = 0; nf < 4; nf++) {
            const int ncol = n0 + wn * 32 + nf * 8 + tg * 2;
            const int c = ncol & (DKK - 1);
            const int h = ncol >> 7;
#pragma unroll
            for (int half = 0; half < 2; half++) {
                const int m = m0 + wm * 64 + mf * 16 + g + half * 8;
                const int s = m & (SS - 1);
                const int b = m >> 11;
                const float x1 = acc[mf][nf][half * 2 + 0];
                const float x2 = acc[mf][nf][half * 2 + 1];
                float* o = &out[((size_t)(b * HH + h) * SS + s) * DKK + c];
                if (z < 2) {
                    const float pos = (float)tok[s];
                    const float freq = expf((float)c * RLOG);
                    float sv, cv;
                    sincosf(pos * freq, &sv, &cv);
                    *(float2*)o = make_float2(x1 * cv - x2 * sv, x1 * sv + x2 * cv);
                } else {
                    *(float2*)o = make_float2(x1, x2);
                }
            }
        }
    }
}

// Output projection GEMM: d_out = AO[4096,2048] @ Wo[2048,2048]
__global__ __launch_bounds__(256, 2) void out_gemm(
    const float* __restrict__ Wo, float* __restrict__ outp)
{
    __shared__ unsigned As[16 * SM_STRIDE];
    __shared__ unsigned Bs[16 * SM_STRIDE];

    const int n0 = blockIdx.x * 128;
    const int m0 = blockIdx.y * 128;
    const int t    = threadIdx.x;
    const int lane = t & 31;
    const int warp = t >> 5;
    const int wm = warp >> 2;
    const int wn = warp & 3;
    const int g  = lane >> 2;
    const int tg = lane & 3;

    const int arow  = t >> 1;
    const int akoff = (t & 1) * 8;
    const int brow  = t >> 4;
    const int bn    = (t & 15) * 8;

    float acc[4][4][4];
#pragma unroll
    for (int mf = 0; mf < 4; mf++)
#pragma unroll
        for (int nf = 0; nf < 4; nf++)
#pragma unroll
            for (int r = 0; r < 4; r++) acc[mf][nf][r] = 0.f;

    for (int k0 = 0; k0 < DM; k0 += 16) {
        const float4 a0 = *(const float4*)&g_AO[(size_t)(m0 + arow) * DM + k0 + akoff];
        const float4 a1 = *(const float4*)&g_AO[(size_t)(m0 + arow) * DM + k0 + akoff + 4];
        const float4 b0 = *(const float4*)&Wo[(size_t)(k0 + brow) * DM + n0 + bn];
        const float4 b1 = *(const float4*)&Wo[(size_t)(k0 + brow) * DM + n0 + bn + 4];
        __syncthreads();
        As[(akoff + 0) * SM_STRIDE + arow] = f2tf32(a0.x);
        As[(akoff + 1) * SM_STRIDE + arow] = f2tf32(a0.y);
        As[(akoff + 2) * SM_STRIDE + arow] = f2tf32(a0.z);
        As[(akoff + 3) * SM_STRIDE + arow] = f2tf32(a0.w);
        As[(akoff + 4) * SM_STRIDE + arow] = f2tf32(a1.x);
        As[(akoff + 5) * SM_STRIDE + arow] = f2tf32(a1.y);
        As[(akoff + 6) * SM_STRIDE + arow] = f2tf32(a1.z);
        As[(akoff + 7) * SM_STRIDE + arow] = f2tf32(a1.w);
        Bs[brow * SM_STRIDE + bn + 0] = f2tf32(b0.x);
        Bs[brow * SM_STRIDE + bn + 1] = f2tf32(b0.y);
        Bs[brow * SM_STRIDE + bn + 2] = f2tf32(b0.z);
        Bs[brow * SM_STRIDE + bn + 3] = f2tf32(b0.w);
        Bs[brow * SM_STRIDE + bn + 4] = f2tf32(b1.x);
        Bs[brow * SM_STRIDE + bn + 5] = f2tf32(b1.y);
        Bs[brow * SM_STRIDE + bn + 6] = f2tf32(b1.z);
        Bs[brow * SM_STRIDE + bn + 7] = f2tf32(b1.w);
        __syncthreads();

#pragma unroll
        for (int ks = 0; ks < 16; ks += 8) {
            unsigned a[4][4];
#pragma unroll
            for (int mf = 0; mf < 4; mf++) {
                const int mb = wm * 64 + mf * 16 + g;
                a[mf][0] = As[(ks + tg) * SM_STRIDE + mb];
                a[mf][1] = As[(ks + tg) * SM_STRIDE + mb + 8];
                a[mf][2] = As[(ks + tg + 4) * SM_STRIDE + mb];
                a[mf][3] = As[(ks + tg + 4) * SM_STRIDE + mb + 8];
            }
            unsigned b[4][2];
#pragma unroll
            for (int nf = 0; nf < 4; nf++) {
                const int nb = wn * 32 + nf * 8 + g;
                b[nf][0] = Bs[(ks + tg) * SM_STRIDE + nb];
                b[nf][1] = Bs[(ks + tg + 4) * SM_STRIDE + nb];
            }
#pragma unroll
            for (int mf = 0; mf < 4; mf++)
#pragma unroll
                for (int nf = 0; nf < 4; nf++)
                    mma_tf32(acc[mf][nf], a[mf], b[nf]);
        }
    }

#pragma unroll
    for (int mf = 0; mf < 4; mf++) {
#pragma unroll
        for (int nf = 0; nf < 4; nf++) {
            const int ncol = n0 + wn * 32 + nf * 8 + tg * 2;
#pragma unroll
            for (int half = 0; half < 2; half++) {
                const int m = m0 + wm * 64 + mf * 16 + g + half * 8;
                *(float2*)&outp[(size_t)m * DM + ncol] =
                    make_float2(acc[mf][nf][half * 2 + 0], acc[mf][nf][half * 2 + 1]);
            }
        }
    }
}

// ---------------------------------------------------------------------------
// Flash attention, fp32, causal. BM=BN=32, 256 threads. (unchanged)
// ---------------------------------------------------------------------------
__global__ __launch_bounds__(256) void attn_kernel()
{
    __shared__ float Qs[32 * 132];
    __shared__ float KV[4480];
    __shared__ float Ps[32 * 36];

    const int qb = blockIdx.x;
    const int bh = blockIdx.y;
    const int q0 = qb * 32;
    const int t  = threadIdx.x;
    const int tx = t & 15;
    const int ty = t >> 4;
    const size_t base = (size_t)bh * SS * DKK;

    const int lrw = t >> 3;
    const int lf  = t & 7;

    {
        const float* qsrc = &g_Q[base + (size_t)(q0 + lrw) * DKK];
#pragma unroll
        for (int j = 0; j < 4; j++) {
            const float4 v = *(const float4*)&qsrc[(lf + j * 8) * 4];
            *(float4*)&Qs[lrw * 132 + (lf + j * 8) * 4] = v;
        }
    }

    float o[2][8];
#pragma unroll
    for (int i = 0; i < 2; i++)
#pragma unroll
        for (int c = 0; c < 8; c++) o[i][c] = 0.f;
    float mrow[2] = {-1e30f, -1e30f};
    float lrow[2] = {0.f, 0.f};
    const float scale = 0.0883883476483f;

    __syncthreads();

    for (int kb = 0; kb <= qb; kb++) {
        const int k0 = kb * 32;
        {
            const float* ks = &g_K[base + (size_t)(k0 + lrw) * DKK];
#pragma unroll
            for (int j = 0; j < 4; j++) {
                const float4 v = *(const float4*)&ks[(lf + j * 8) * 4];
                const int c0 = (lf + j * 8) * 4;
                KV[(c0 + 0) * 34 + lrw] = v.x;
                KV[(c0 + 1) * 34 + lrw] = v.y;
                KV[(c0 + 2) * 34 + lrw] = v.z;
                KV[(c0 + 3) * 34 + lrw] = v.w;
            }
        }
        __syncthreads();

        float sacc[2][2] = {{0.f, 0.f}, {0.f, 0.f}};
#pragma unroll 8
        for (int d = 0; d < DKK; d++) {
            const float qv0 = Qs[(ty * 2 + 0) * 132 + d];
            const float qv1 = Qs[(ty * 2 + 1) * 132 + d];
            const float2 kk = *(const float2*)&KV[d * 34 + tx * 2];
            sacc[0][0] += qv0 * kk.x;
            sacc[0][1] += qv0 * kk.y;
            sacc[1][0] += qv1 * kk.x;
            sacc[1][1] += qv1 * kk.y;
        }

        const bool diag = (kb == qb);
#pragma unroll
        for (int i = 0; i < 2; i++) {
            const int qi = q0 + ty * 2 + i;
            float s0 = sacc[i][0] * scale;
            float s1 = sacc[i][1] * scale;
            if (diag) {
                if (k0 + tx * 2 + 0 > qi) s0 = -1e30f;
                if (k0 + tx * 2 + 1 > qi) s1 = -1e30f;
            }
            float mx = fmaxf(s0, s1);
#pragma unroll
            for (int off = 1; off < 16; off <<= 1)
                mx = fmaxf(mx, __shfl_xor_sync(0xffffffffu, mx, off));
            const float mnew = fmaxf(mrow[i], mx);
            const float alpha = expf(mrow[i] - mnew);
            const float p0 = expf(s0 - mnew);
            const float p1 = expf(s1 - mnew);
            float ls = p0 + p1;
#pragma unroll
            for (int off = 1; off < 16; off <<= 1)
                ls += __shfl_xor_sync(0xffffffffu, ls, off);
            lrow[i] = lrow[i] * alpha + ls;
            mrow[i] = mnew;
#pragma unroll
            for (int c = 0; c < 8; c++) o[i][c] *= alpha;
            Ps[(ty * 2 + i) * 36 + tx * 2 + 0] = p0;
            Ps[(ty * 2 + i) * 36 + tx * 2 + 1] = p1;
        }
        __syncthreads();

        {
            const float* vs = &g_V[base + (size_t)(k0 + lrw) * DKK];
#pragma unroll
            for (int j = 0; j < 4; j++) {
                const float4 v = *(const float4*)&vs[(lf + j * 8) * 4];
                *(float4*)&KV[lrw * 132 + (lf + j * 8) * 4] = v;
            }
        }
        __syncthreads();

#pragma unroll 8
        for (int j = 0; j < 32; j++) {
            const float p0 = Ps[(ty * 2 + 0) * 36 + j];
            const float p1 = Ps[(ty * 2 + 1) * 36 + j];
            const float4 va = *(const float4*)&KV[j * 132 + tx * 4];
            const float4 vb = *(const float4*)&KV[j * 132 + 64 + tx * 4];
            o[0][0] += p0 * va.x; o[0][1] += p0 * va.y;
            o[0][2] += p0 * va.z; o[0][3] += p0 * va.w;
            o[0][4] += p0 * vb.x; o[0][5] += p0 * vb.y;
            o[0][6] += p0 * vb.z; o[0][7] += p0 * vb.w;
            o[1][0] += p1 * va.x; o[1][1] += p1 * va.y;
            o[1][2] += p1 * va.z; o[1][3] += p1 * va.w;
            o[1][4] += p1 * vb.x; o[1][5] += p1 * vb.y;
            o[1][6] += p1 * vb.z; o[1][7] += p1 * vb.w;
        }
        __syncthreads();
    }

    const int b = bh >> 4;
    const int h = bh & 15;
#pragma unroll
    for (int i = 0; i < 2; i++) {
        const float inv = 1.f / lrow[i];
        const int s = q0 + ty * 2 + i;
        const size_t ob = ((size_t)b * SS + s) * DM + h * DKK;
        *(float4*)&g_AO[ob + tx * 4] =
            make_float4(o[i][0] * inv, o[i][1] * inv, o[i][2] * inv, o[i][3] * inv);
        *(float4*)&g_AO[ob + 64 + tx * 4] =
            make_float4(o[i][4] * inv, o[i][5] * inv, o[i][6] * inv, o[i][7] * inv);
    }
}

// ---------------------------------------------------------------------------
extern "C" void kernel_launch(void* const* d_in, const int* in_sizes, int n_in,
                              void* d_out, int out_size)
{
    const float* x  = (const float*)d_in[0];
    const float* Wq = (const float*)d_in[1];
    const float* Wk = (const float*)d_in[2];
    const float* Wv = (const float*)d_in[3];
    const float* Wo = (const float*)d_in[4];
    const int*  tok = (const int*)d_in[5];
    float* outp = (float*)d_out;

    qkv_gemm<<<dim3(DM / 128, MT / 128, 3), 256>>>(x, Wq, Wk, Wv, tok);
    attn_kernel<<<dim3(SS / 32, BB * HH), 256>>>();
    out_gemm<<<dim3(DM / 128, MT / 128), 256>>>(Wo, outp);
}

// round 5
// speedup vs baseline: 2.5903x; 1.5953x over previous
#include <cuda_runtime.h>
#include <math.h>

#define BB 2
#define HH 16
#define SS 2048
#define DKK 128
#define DM 2048
#define MT (BB*SS) // 4096

// Scratch (device globals: allocation-guard-safe)
__device__ float g_Q[BB*HH*SS*DKK];
__device__ float g_K[BB*HH*SS*DKK];
__device__ float g_V[BB*HH*SS*DKK];
__device__ float g_AO[MT*DM];

// ---------------------------------------------------------------------------
// TF32 helpers
// ---------------------------------------------------------------------------
__device__ __forceinline__ unsigned f2tf32(float x) {
    unsigned u;
    asm("cvt.rna.tf32.f32 %0, %1;" : "=r"(u) : "f"(x));
    return u;
}

__device__ __forceinline__ void mma_tf32(float* c, const unsigned* a, const unsigned* b) {
    asm volatile(
        "mma.sync.aligned.m16n8k8.row.col.f32.tf32.tf32.f32 "
        "{%0,%1,%2,%3}, {%4,%5,%6,%7}, {%8,%9}, {%0,%1,%2,%3};\n"
        : "+f"(c[0]), "+f"(c[1]), "+f"(c[2]), "+f"(c[3])
        : "r"(a[0]), "r"(a[1]), "r"(a[2]), "r"(a[3]), "r"(b[0]), "r"(b[1]));
}

// ---------------------------------------------------------------------------
// TF32 tensor-core GEMM core (unchanged from R3).
// Block tile 128m x 128n x 16k, 256 threads = 8 warps (2m x 4n),
// warp tile 64x32 = 4x4 m16n8k8 fragments.
// ---------------------------------------------------------------------------
#define SM_STRIDE 136

// Fused QKV projection + RoPE epilogue. z=0:Q(rope) 1:K(rope) 2:V
__global__ __launch_bounds__(256, 2) void qkv_gemm(
    const float* __restrict__ X,
    const float* __restrict__ Wq, const float* __restrict__ Wk,
    const float* __restrict__ Wv,
    const int* __restrict__ tok)
{
    __shared__ unsigned As[16 * SM_STRIDE];
    __shared__ unsigned Bs[16 * SM_STRIDE];

    const int z = blockIdx.z;
    const float* __restrict__ W = (z == 0) ? Wq : ((z == 1) ? Wk : Wv);
    float* __restrict__ out = (z == 0) ? g_Q : ((z == 1) ? g_K : g_V);

    const int n0 = blockIdx.x * 128;
    const int m0 = blockIdx.y * 128;
    const int t    = threadIdx.x;
    const int lane = t & 31;
    const int warp = t >> 5;
    const int wm = warp >> 2;
    const int wn = warp & 3;
    const int g  = lane >> 2;
    const int tg = lane & 3;

    const int arow  = t >> 1;
    const int akoff = (t & 1) * 8;
    const int brow  = t >> 4;
    const int bn    = (t & 15) * 8;

    float acc[4][4][4];
#pragma unroll
    for (int mf = 0; mf < 4; mf++)
#pragma unroll
        for (int nf = 0; nf < 4; nf++)
#pragma unroll
            for (int r = 0; r < 4; r++) acc[mf][nf][r] = 0.f;

    for (int k0 = 0; k0 < DM; k0 += 16) {
        const float4 a0 = *(const float4*)&X[(size_t)(m0 + arow) * DM + k0 + akoff];
        const float4 a1 = *(const float4*)&X[(size_t)(m0 + arow) * DM + k0 + akoff + 4];
        const float4 b0 = *(const float4*)&W[(size_t)(k0 + brow) * DM + n0 + bn];
        const float4 b1 = *(const float4*)&W[(size_t)(k0 + brow) * DM + n0 + bn + 4];
        __syncthreads();
        As[(akoff + 0) * SM_STRIDE + arow] = f2tf32(a0.x);
        As[(akoff + 1) * SM_STRIDE + arow] = f2tf32(a0.y);
        As[(akoff + 2) * SM_STRIDE + arow] = f2tf32(a0.z);
        As[(akoff + 3) * SM_STRIDE + arow] = f2tf32(a0.w);
        As[(akoff + 4) * SM_STRIDE + arow] = f2tf32(a1.x);
        As[(akoff + 5) * SM_STRIDE + arow] = f2tf32(a1.y);
        As[(akoff + 6) * SM_STRIDE + arow] = f2tf32(a1.z);
        As[(akoff + 7) * SM_STRIDE + arow] = f2tf32(a1.w);
        Bs[brow * SM_STRIDE + bn + 0] = f2tf32(b0.x);
        Bs[brow * SM_STRIDE + bn + 1] = f2tf32(b0.y);
        Bs[brow * SM_STRIDE + bn + 2] = f2tf32(b0.z);
        Bs[brow * SM_STRIDE + bn + 3] = f2tf32(b0.w);
        Bs[brow * SM_STRIDE + bn + 4] = f2tf32(b1.x);
        Bs[brow * SM_STRIDE + bn + 5] = f2tf32(b1.y);
        Bs[brow * SM_STRIDE + bn + 6] = f2tf32(b1.z);
        Bs[brow * SM_STRIDE + bn + 7] = f2tf32(b1.w);
        __syncthreads();

#pragma unroll
        for (int ks = 0; ks < 16; ks += 8) {
            unsigned a[4][4];
#pragma unroll
            for (int mf = 0; mf < 4; mf++) {
                const int mb = wm * 64 + mf * 16 + g;
                a[mf][0] = As[(ks + tg) * SM_STRIDE + mb];
                a[mf][1] = As[(ks + tg) * SM_STRIDE + mb + 8];
                a[mf][2] = As[(ks + tg + 4) * SM_STRIDE + mb];
                a[mf][3] = As[(ks + tg + 4) * SM_STRIDE + mb + 8];
            }
            unsigned b[4][2];
#pragma unroll
            for (int nf = 0; nf < 4; nf++) {
                const int nb = wn * 32 + nf * 8 + g;
                b[nf][0] = Bs[(ks + tg) * SM_STRIDE + nb];
                b[nf][1] = Bs[(ks + tg + 4) * SM_STRIDE + nb];
            }
#pragma unroll
            for (int mf = 0; mf < 4; mf++)
#pragma unroll
                for (int nf = 0; nf < 4; nf++)
                    mma_tf32(acc[mf][nf], a[mf], b[nf]);
        }
    }

    const float RLOG = -0.07195578146f; // -ln(10000)/128
#pragma unroll
    for (int mf = 0; mf < 4; mf++) {
#pragma unroll
        for (int nf = 0; nf < 4; nf++) {
            const int ncol = n0 + wn * 32 + nf * 8 + tg * 2;
            const int c = ncol & (DKK - 1);
            const int h = ncol >> 7;
#pragma unroll
            for (int half = 0; half < 2; half++) {
                const int m = m0 + wm * 64 + mf * 16 + g + half * 8;
                const int s = m & (SS - 1);
                const int b = m >> 11;
                const float x1 = acc[mf][nf][half * 2 + 0];
                const float x2 = acc[mf][nf][half * 2 + 1];
                float* o = &out[((size_t)(b * HH + h) * SS + s) * DKK + c];
                if (z < 2) {
                    const float pos = (float)tok[s];
                    const float freq = expf((float)c * RLOG);
                    float sv, cv;
                    sincosf(pos * freq, &sv, &cv);
                    *(float2*)o = make_float2(x1 * cv - x2 * sv, x1 * sv + x2 * cv);
                } else {
                    *(float2*)o = make_float2(x1, x2);
                }
            }
        }
    }
}

// Output projection GEMM: d_out = AO[4096,2048] @ Wo[2048,2048]
__global__ __launch_bounds__(256, 2) void out_gemm(
    const float* __restrict__ Wo, float* __restrict__ outp)
{
    __shared__ unsigned As[16 * SM_STRIDE];
    __shared__ unsigned Bs[16 * SM_STRIDE];

    const int n0 = blockIdx.x * 128;
    const int m0 = blockIdx.y * 128;
    const int t    = threadIdx.x;
    const int lane = t & 31;
    const int warp = t >> 5;
    const int wm = warp >> 2;
    const int wn = warp & 3;
    const int g  = lane >> 2;
    const int tg = lane & 3;

    const int arow  = t >> 1;
    const int akoff = (t & 1) * 8;
    const int brow  = t >> 4;
    const int bn    = (t & 15) * 8;

    float acc[4][4][4];
#pragma unroll
    for (int mf = 0; mf < 4; mf++)
#pragma unroll
        for (int nf = 0; nf < 4; nf++)
#pragma unroll
            for (int r = 0; r < 4; r++) acc[mf][nf][r] = 0.f;

    for (int k0 = 0; k0 < DM; k0 += 16) {
        const float4 a0 = *(const float4*)&g_AO[(size_t)(m0 + arow) * DM + k0 + akoff];
        const float4 a1 = *(const float4*)&g_AO[(size_t)(m0 + arow) * DM + k0 + akoff + 4];
        const float4 b0 = *(const float4*)&Wo[(size_t)(k0 + brow) * DM + n0 + bn];
        const float4 b1 = *(const float4*)&Wo[(size_t)(k0 + brow) * DM + n0 + bn + 4];
        __syncthreads();
        As[(akoff + 0) * SM_STRIDE + arow] = f2tf32(a0.x);
        As[(akoff + 1) * SM_STRIDE + arow] = f2tf32(a0.y);
        As[(akoff + 2) * SM_STRIDE + arow] = f2tf32(a0.z);
        As[(akoff + 3) * SM_STRIDE + arow] = f2tf32(a0.w);
        As[(akoff + 4) * SM_STRIDE + arow] = f2tf32(a1.x);
        As[(akoff + 5) * SM_STRIDE + arow] = f2tf32(a1.y);
        As[(akoff + 6) * SM_STRIDE + arow] = f2tf32(a1.z);
        As[(akoff + 7) * SM_STRIDE + arow] = f2tf32(a1.w);
        Bs[brow * SM_STRIDE + bn + 0] = f2tf32(b0.x);
        Bs[brow * SM_STRIDE + bn + 1] = f2tf32(b0.y);
        Bs[brow * SM_STRIDE + bn + 2] = f2tf32(b0.z);
        Bs[brow * SM_STRIDE + bn + 3] = f2tf32(b0.w);
        Bs[brow * SM_STRIDE + bn + 4] = f2tf32(b1.x);
        Bs[brow * SM_STRIDE + bn + 5] = f2tf32(b1.y);
        Bs[brow * SM_STRIDE + bn + 6] = f2tf32(b1.z);
        Bs[brow * SM_STRIDE + bn + 7] = f2tf32(b1.w);
        __syncthreads();

#pragma unroll
        for (int ks = 0; ks < 16; ks += 8) {
            unsigned a[4][4];
#pragma unroll
            for (int mf = 0; mf < 4; mf++) {
                const int mb = wm * 64 + mf * 16 + g;
                a[mf][0] = As[(ks + tg) * SM_STRIDE + mb];
                a[mf][1] = As[(ks + tg) * SM_STRIDE + mb + 8];
                a[mf][2] = As[(ks + tg + 4) * SM_STRIDE + mb];
                a[mf][3] = As[(ks + tg + 4) * SM_STRIDE + mb + 8];
            }
            unsigned b[4][2];
#pragma unroll
            for (int nf = 0; nf < 4; nf++) {
                const int nb = wn * 32 + nf * 8 + g;
                b[nf][0] = Bs[(ks + tg) * SM_STRIDE + nb];
                b[nf][1] = Bs[(ks + tg + 4) * SM_STRIDE + nb];
            }
#pragma unroll
            for (int mf = 0; mf < 4; mf++)
#pragma unroll
                for (int nf = 0; nf < 4; nf++)
                    mma_tf32(acc[mf][nf], a[mf], b[nf]);
        }
    }

#pragma unroll
    for (int mf = 0; mf < 4; mf++) {
#pragma unroll
        for (int nf = 0; nf < 4; nf++) {
            const int ncol = n0 + wn * 32 + nf * 8 + tg * 2;
#pragma unroll
            for (int half = 0; half < 2; half++) {
                const int m = m0 + wm * 64 + mf * 16 + g + half * 8;
                *(float2*)&outp[(size_t)m * DM + ncol] =
                    make_float2(acc[mf][nf][half * 2 + 0], acc[mf][nf][half * 2 + 1]);
            }
        }
    }
}

// ---------------------------------------------------------------------------
// TF32 flash attention, causal.
// CTA: 256 threads = 8 warps; BM=128 (16 q-rows per warp), BN=64, D=128.
// smem (u32 units):
//   Qs [128][132]   a-frags, banks g*4+tg         (16896)
//   Ks [128 d][72]  K^T, b-frags banks tg*8+g     ( 9216)
//   Vs [64 key][136] V, b-frags banks tg*8+g      ( 8704)
//   Ps [8][16][68]  warp-private P c->a relayout  ( 8704)
// total 43520 u32 = 174080 B (dynamic).
// ---------------------------------------------------------------------------
#define QS_ST 132
#define KS_ST 72
#define VS_ST 136
#define PS_ST 68
#define QS_OFF 0
#define KS_OFF 16896
#define VS_OFF 26112
#define PS_OFF 34816
#define ATTN_SMEM_BYTES 174080

__global__ __launch_bounds__(256, 1) void attn_tc()
{
    extern __shared__ unsigned sm[];
    unsigned* Qs = sm + QS_OFF;
    unsigned* Ks = sm + KS_OFF;
    unsigned* Vs = sm + VS_OFF;
    unsigned* Ps = sm + PS_OFF;

    const int qb = 15 - blockIdx.x;      // big blocks first
    const int bh = blockIdx.y;
    const int q0 = qb * 128;
    const int t    = threadIdx.x;
    const int lane = t & 31;
    const int w    = t >> 5;             // 0..7
    const int g    = lane >> 2;          // 0..7
    const int tg   = lane & 3;           // 0..3
    const size_t base = (size_t)bh * SS * DKK;
    const float scale = 0.08838834764831845f;  // 1/sqrt(128)

    // Load Q tile [128][128], pre-scaled + tf32, stride 132
    {
        const int r = t >> 1;
        const int cb = (t & 1) * 64;
        const float* qsrc = &g_Q[base + (size_t)(q0 + r) * DKK + cb];
#pragma unroll
        for (int j = 0; j < 16; j++) {
            const float4 v = *(const float4*)&qsrc[j * 4];
            uint4 u;
            u.x = f2tf32(v.x * scale);
            u.y = f2tf32(v.y * scale);
            u.z = f2tf32(v.z * scale);
            u.w = f2tf32(v.w * scale);
            *(uint4*)&Qs[r * QS_ST + cb + j * 4] = u;
        }
    }

    float o[16][4];
#pragma unroll
    for (int nf = 0; nf < 16; nf++)
#pragma unroll
        for (int r = 0; r < 4; r++) o[nf][r] = 0.f;
    float mrow[2] = {-1e30f, -1e30f};
    float lrow[2] = {0.f, 0.f};

    unsigned* Psw = Ps + w * 16 * PS_ST;
    const int nkb = 2 * qb + 2;

    for (int kb = 0; kb < nkb; kb++) {
        const int k0 = kb * 64;
        __syncthreads();   // prior-iter smem reads done (covers Q-load sync too)

        // Load K tile -> Ks[d][key] (transposed), tf32
        {
            const int key = t & 63;
            const int d0 = (t >> 6) * 32;
            const float* ksrc = &g_K[base + (size_t)(k0 + key) * DKK + d0];
#pragma unroll
            for (int j = 0; j < 8; j++) {
                const float4 v = *(const float4*)&ksrc[j * 4];
                Ks[(d0 + j * 4 + 0) * KS_ST + key] = f2tf32(v.x);
                Ks[(d0 + j * 4 + 1) * KS_ST + key] = f2tf32(v.y);
                Ks[(d0 + j * 4 + 2) * KS_ST + key] = f2tf32(v.z);
                Ks[(d0 + j * 4 + 3) * KS_ST + key] = f2tf32(v.w);
            }
        }
        // Load V tile -> Vs[key][d], tf32
        {
            const int vr = t >> 2;
            const int vc = (t & 3) * 32;
            const float* vsrc = &g_V[base + (size_t)(k0 + vr) * DKK + vc];
#pragma unroll
            for (int j = 0; j < 8; j++) {
                const float4 v = *(const float4*)&vsrc[j * 4];
                uint4 u;
                u.x = f2tf32(v.x); u.y = f2tf32(v.y);
                u.z = f2tf32(v.z); u.w = f2tf32(v.w);
                *(uint4*)&Vs[vr * VS_ST + vc + j * 4] = u;
            }
        }
        __syncthreads();

        // S = Q K^T  (16x64 per warp)
        float sacc[8][4];
#pragma unroll
        for (int nf = 0; nf < 8; nf++)
#pragma unroll
            for (int r = 0; r < 4; r++) sacc[nf][r] = 0.f;

#pragma unroll 4
        for (int ks = 0; ks < 16; ks++) {
            unsigned a[4];
            const unsigned* q0p = &Qs[(w * 16 + g) * QS_ST + ks * 8];
            const unsigned* q1p = &Qs[(w * 16 + g + 8) * QS_ST + ks * 8];
            a[0] = q0p[tg];
            a[1] = q1p[tg];
            a[2] = q0p[tg + 4];
            a[3] = q1p[tg + 4];
#pragma unroll
            for (int nf = 0; nf < 8; nf++) {
                unsigned b[2];
                b[0] = Ks[(ks * 8 + tg) * KS_ST + nf * 8 + g];
                b[1] = Ks[(ks * 8 + tg + 4) * KS_ST + nf * 8 + g];
                mma_tf32(sacc[nf], a, b);
            }
        }

        // Causal mask (only needed for the last 2 K-blocks)
        if (kb >= nkb - 2) {
#pragma unroll
            for (int nf = 0; nf < 8; nf++) {
#pragma unroll
                for (int jj = 0; jj < 4; jj++) {
                    const int col = k0 + nf * 8 + tg * 2 + (jj & 1);
                    const int row = q0 + w * 16 + g + (jj >> 1) * 8;
                    if (col > row) sacc[nf][jj] = -1e30f;
                }
            }
        }

        // Online softmax (rows g and g+8)
#pragma unroll
        for (int i = 0; i < 2; i++) {
            float mx = -1e30f;
#pragma unroll
            for (int nf = 0; nf < 8; nf++)
                mx = fmaxf(mx, fmaxf(sacc[nf][2 * i], sacc[nf][2 * i + 1]));
            mx = fmaxf(mx, __shfl_xor_sync(0xffffffffu, mx, 1));
            mx = fmaxf(mx, __shfl_xor_sync(0xffffffffu, mx, 2));
            const float mnew = fmaxf(mrow[i], mx);
            const float alpha = __expf(mrow[i] - mnew);
            float ls = 0.f;
#pragma unroll
            for (int nf = 0; nf < 8; nf++) {
                const float p0 = __expf(sacc[nf][2 * i] - mnew);
                const float p1 = __expf(sacc[nf][2 * i + 1] - mnew);
                ls += p0 + p1;
                uint2 pu;
                pu.x = f2tf32(p0);
                pu.y = f2tf32(p1);
                *(uint2*)&Psw[(g + i * 8) * PS_ST + nf * 8 + tg * 2] = pu;
            }
            ls += __shfl_xor_sync(0xffffffffu, ls, 1);
            ls += __shfl_xor_sync(0xffffffffu, ls, 2);
            lrow[i] = lrow[i] * alpha + ls;
            mrow[i] = mnew;
#pragma unroll
            for (int nf = 0; nf < 16; nf++) {
                o[nf][2 * i]     *= alpha;
                o[nf][2 * i + 1] *= alpha;
            }
        }
        __syncwarp();

        // O += P V  (16x128 per warp)
#pragma unroll 4
        for (int ks = 0; ks < 8; ks++) {
            unsigned a[4];
            const unsigned* p0p = &Psw[g * PS_ST + ks * 8];
            const unsigned* p1p = &Psw[(g + 8) * PS_ST + ks * 8];
            a[0] = p0p[tg];
            a[1] = p1p[tg];
            a[2] = p0p[tg + 4];
            a[3] = p1p[tg + 4];
#pragma unroll
            for (int nf = 0; nf < 16; nf++) {
                unsigned b[2];
                b[0] = Vs[(ks * 8 + tg) * VS_ST + nf * 8 + g];
                b[1] = Vs[(ks * 8 + tg + 4) * VS_ST + nf * 8 + g];
                mma_tf32(o[nf], a, b);
            }
        }
    }

    // Epilogue: normalize, write to [B,S,H*128]
    const int b = bh >> 4;
    const int h = bh & 15;
#pragma unroll
    for (int i = 0; i < 2; i++) {
        const float inv = 1.f / lrow[i];
        const int s = q0 + w * 16 + g + i * 8;
        float* obase = &g_AO[((size_t)b * SS + s) * DM + h * DKK];
#pragma unroll
        for (int nf = 0; nf < 16; nf++) {
            *(float2*)&obase[nf * 8 + tg * 2] =
                make_float2(o[nf][2 * i] * inv, o[nf][2 * i + 1] * inv);
        }
    }
}

// ---------------------------------------------------------------------------
extern "C" void kernel_launch(void* const* d_in, const int* in_sizes, int n_in,
                              void* d_out, int out_size)
{
    const float* x  = (const float*)d_in[0];
    const float* Wq = (const float*)d_in[1];
    const float* Wk = (const float*)d_in[2];
    const float* Wv = (const float*)d_in[3];
    const float* Wo = (const float*)d_in[4];
    const int*  tok = (const int*)d_in[5];
    float* outp = (float*)d_out;

    cudaFuncSetAttribute(attn_tc, cudaFuncAttributeMaxDynamicSharedMemorySize,
                         ATTN_SMEM_BYTES);

    qkv_gemm<<<dim3(DM / 128, MT / 128, 3), 256>>>(x, Wq, Wk, Wv, tok);
    attn_tc<<<dim3(SS / 128, BB * HH), 256, ATTN_SMEM_BYTES>>>();
    out_gemm<<<dim3(DM / 128, MT / 128), 256>>>(Wo, outp);
}